// round 11
// baseline (speedup 1.0000x reference)
#include <cuda_runtime.h>
#include <math.h>

#define BATCH 2
#define NPTS 4096
#define MPTS 4096
#define NSTEPS 8
#define TOLER 1e-6f

#define TPB 128
#define NCHB 32                         // 32 chunks of 128 queries per batch
#define NN_BLKS (BATCH * NCHB)          // 64
#define TOTAL_BLKS (NN_BLKS + 1)

// spatial grid over targets: 64^3 cells, h=0.25, covering [-8,8)
#define G 64
#define NC (G * G * G)
#define CELL_H 0.25f
#define INV_H 4.0f
#define GRID_LO 8.0f

// ---------------- device state ----------------
__device__ float4 g_tgt4[BATCH * MPTS];       // original targets (x,y,z,|t|^2)
__device__ float4 g_sorted[BATCH * MPTS];     // grid-sorted targets (x,y,z,idx-bits)
__device__ int g_cs[BATCH][NC + 1];           // cell start offsets (prefix)
__device__ int g_fill[BATCH][NC + 1];         // scatter cursors
__device__ unsigned g_cnt[BATCH][NC];         // per-cell counts
__device__ float g_Rcum[BATCH][9];
__device__ float g_tcum[BATCH][3];
__device__ float g_err[BATCH];
__device__ int g_done;
__device__ unsigned g_tailcnt;
__device__ float g_part[NN_BLKS][16];

__device__ __forceinline__ int cell_of(float v) {
    int c = (int)floorf((v + GRID_LO) * INV_H);
    return min(G - 1, max(0, c));
}

// ---------------- init chain ----------------
__global__ void zero_kernel() {
    int i = blockIdx.x * blockDim.x + threadIdx.x;
    for (int j = i; j < BATCH * NC; j += gridDim.x * blockDim.x) {
        g_cnt[j / NC][j % NC] = 0u;
    }
    if (i == 0) { g_done = 0; g_tailcnt = 0u; }
    if (i < BATCH) {
        g_err[i] = 0.0f;
        float* R = g_Rcum[i];
        R[0] = 1.f; R[1] = 0.f; R[2] = 0.f;
        R[3] = 0.f; R[4] = 1.f; R[5] = 0.f;
        R[6] = 0.f; R[7] = 0.f; R[8] = 1.f;
        g_tcum[i][0] = 0.f; g_tcum[i][1] = 0.f; g_tcum[i][2] = 0.f;
    }
}

__global__ void count_kernel(const float* __restrict__ ptgt) {
    int i = blockIdx.x * blockDim.x + threadIdx.x;   // 0..8191
    if (i >= BATCH * MPTS) return;
    float x = ptgt[i * 3 + 0];
    float y = ptgt[i * 3 + 1];
    float z = ptgt[i * 3 + 2];
    g_tgt4[i] = make_float4(x, y, z, x * x + y * y + z * z);
    int c = (cell_of(z) * G + cell_of(y)) * G + cell_of(x);
    atomicAdd(&g_cnt[i >> 12][c], 1u);
}

__global__ __launch_bounds__(1024) void scan_kernel() {
    const int b = blockIdx.x;
    const int t = threadIdx.x;
    const int CH = NC / 1024;            // 256 cells per thread
    const int base = t * CH;

    unsigned sum = 0;
    for (int i = 0; i < CH; i++) sum += g_cnt[b][base + i];

    __shared__ unsigned a[1024];
    a[t] = sum;
    __syncthreads();
    for (int off = 1; off < 1024; off <<= 1) {
        unsigned v = (t >= off) ? a[t - off] : 0u;
        __syncthreads();
        a[t] += v;
        __syncthreads();
    }
    unsigned run = a[t] - sum;           // exclusive prefix

    for (int i = 0; i < CH; i++) {
        unsigned c = g_cnt[b][base + i];
        g_cs[b][base + i] = (int)run;
        g_fill[b][base + i] = (int)run;
        run += c;
    }
    if (t == 1023) g_cs[b][NC] = (int)run;   // == MPTS
}

__global__ void scatter_kernel(const float* __restrict__ ptgt) {
    int i = blockIdx.x * blockDim.x + threadIdx.x;
    if (i >= BATCH * MPTS) return;
    const int b = i >> 12;
    float x = ptgt[i * 3 + 0];
    float y = ptgt[i * 3 + 1];
    float z = ptgt[i * 3 + 2];
    int c = (cell_of(z) * G + cell_of(y)) * G + cell_of(x);
    int pos = atomicAdd(&g_fill[b][c], 1);
    g_sorted[(b << 12) + pos] = make_float4(x, y, z, __uint_as_float((unsigned)(i & (MPTS - 1))));
}

// ---------------- float Horn quaternion Kabsch ----------------
__device__ __forceinline__ void matmul4(float* C, const float* A, const float* Bm) {
#pragma unroll
    for (int i = 0; i < 4; i++)
#pragma unroll
        for (int j = 0; j < 4; j++) {
            float a = 0.f;
#pragma unroll
            for (int k = 0; k < 4; k++) a = __fmaf_rn(A[i * 4 + k], Bm[k * 4 + j], a);
            C[i * 4 + j] = a;
        }
}

__device__ void solve_horn_f(const float* S, float* Rn, float* tn) {
    const float n = (float)NPTS;
    const float inv = 1.0f / n;
    const float pmx = S[0] * inv, pmy = S[1] * inv, pmz = S[2] * inv;
    const float qmx = S[3] * inv, qmy = S[4] * inv, qmz = S[5] * inv;

    const float Sxx = S[6]  - n * pmx * qmx, Sxy = S[7]  - n * pmx * qmy, Sxz = S[8]  - n * pmx * qmz;
    const float Syx = S[9]  - n * pmy * qmx, Syy = S[10] - n * pmy * qmy, Syz = S[11] - n * pmy * qmz;
    const float Szx = S[12] - n * pmz * qmx, Szy = S[13] - n * pmz * qmy, Szz = S[14] - n * pmz * qmz;

    float K[16];
    K[0]  = Sxx + Syy + Szz; K[1]  = Syz - Szy;        K[2]  = Szx - Sxz;       K[3]  = Sxy - Syx;
    K[5]  = Sxx - Syy - Szz; K[6]  = Sxy + Syx;        K[7]  = Szx + Sxz;
    K[10] = -Sxx + Syy - Szz; K[11] = Syz + Szy;
    K[15] = -Sxx - Syy + Szz;
    K[4] = K[1]; K[8] = K[2]; K[12] = K[3]; K[9] = K[6]; K[13] = K[7]; K[14] = K[11];

    float fro = 0.f;
#pragma unroll
    for (int i = 0; i < 16; i++) fro += K[i] * K[i];
    const float sc = rsqrtf(fro + 1e-30f);

    float Kf[16];
#pragma unroll
    for (int i = 0; i < 16; i++) Kf[i] = K[i] * sc;
    Kf[0] += 1.f; Kf[5] += 1.f; Kf[10] += 1.f; Kf[15] += 1.f;  // eigs in [0,2]

    float K2[16], K4[16];
    matmul4(K2, Kf, Kf);
    matmul4(K4, K2, K2);

    float v0 = 1.f, v1 = 0.02f, v2 = 0.03f, v3 = 0.04f;
#pragma unroll 4
    for (int it = 0; it < 48; it++) {
        float w0 = K4[0]  * v0 + K4[1]  * v1 + K4[2]  * v2 + K4[3]  * v3;
        float w1 = K4[4]  * v0 + K4[5]  * v1 + K4[6]  * v2 + K4[7]  * v3;
        float w2 = K4[8]  * v0 + K4[9]  * v1 + K4[10] * v2 + K4[11] * v3;
        float w3 = K4[12] * v0 + K4[13] * v1 + K4[14] * v2 + K4[15] * v3;
        if ((it & 3) == 3) {
            float r = rsqrtf(w0 * w0 + w1 * w1 + w2 * w2 + w3 * w3 + 1e-30f);
            w0 *= r; w1 *= r; w2 *= r; w3 *= r;
        }
        v0 = w0; v1 = w1; v2 = w2; v3 = w3;
    }

    const float qw = v0, qx = v1, qy = v2, qz = v3;
    const float nn = qw * qw + qx * qx + qy * qy + qz * qz;
    const float s2 = 2.0f / nn;
    Rn[0] = 1.f - s2 * (qy * qy + qz * qz); Rn[1] = s2 * (qx * qy - qw * qz); Rn[2] = s2 * (qx * qz + qw * qy);
    Rn[3] = s2 * (qx * qy + qw * qz); Rn[4] = 1.f - s2 * (qx * qx + qz * qz); Rn[5] = s2 * (qy * qz - qw * qx);
    Rn[6] = s2 * (qx * qz - qw * qy); Rn[7] = s2 * (qy * qz + qw * qx); Rn[8] = 1.f - s2 * (qx * qx + qy * qy);

    tn[0] = qmx - (Rn[0] * pmx + Rn[1] * pmy + Rn[2] * pmz);
    tn[1] = qmy - (Rn[3] * pmx + Rn[4] * pmy + Rn[5] * pmz);
    tn[2] = qmz - (Rn[6] * pmx + Rn[7] * pmy + Rn[8] * pmz);
}

// ---------------- sync helpers ----------------
__device__ __forceinline__ void arrive(unsigned* p) {
    unsigned old;
    asm volatile("atom.acq_rel.gpu.global.add.u32 %0, [%1], %2;"
                 : "=r"(old) : "l"(p), "r"(1u) : "memory");
}
__device__ __forceinline__ void wait_ge(unsigned* p, unsigned target) {
    unsigned v;
    for (;;) {
        asm volatile("ld.acquire.gpu.global.u32 %0, [%1];"
                     : "=r"(v) : "l"(p) : "memory");
        if (v >= target) break;
        __nanosleep(32);
    }
}

// ---------------- one ICP step: grid-NN + reduce (64 blks) -> final solve ----------------
__global__ __launch_bounds__(TPB) void step_kernel(const float* __restrict__ psrc,
                                                   float* __restrict__ out, int step) {
    const int tid = threadIdx.x;
    const int bx = blockIdx.x;

    // =================== NN + reduce blocks ===================
    if (bx < NN_BLKS) {
        __shared__ float sRt[12];
        __shared__ int sdone;
        __shared__ float sm[4][16];

        const int b = bx >> 5;
        const int chunk = bx & 31;

        if (tid < 12)
            sRt[tid] = (tid < 9) ? g_Rcum[b][tid] : g_tcum[b][tid - 9];
        if (tid == 0) sdone = g_done;
        __syncthreads();

        float v[16];
#pragma unroll
        for (int k = 0; k < 16; k++) v[k] = 0.f;

        if (!sdone) {
            const int n = chunk * TPB + tid;
            const float* ps = psrc + ((size_t)b * NPTS + n) * 3;
            const float x = ps[0], y = ps[1], z = ps[2];
            const float px = sRt[0] * x + sRt[1] * y + sRt[2] * z + sRt[9];
            const float py = sRt[3] * x + sRt[4] * y + sRt[5] * z + sRt[10];
            const float pz = sRt[6] * x + sRt[7] * y + sRt[8] * z + sRt[11];

            const int cx = cell_of(px), cy = cell_of(py), cz = cell_of(pz);
            const int* cs = g_cs[b];
            const float4* sp = g_sorted + (b << 12);

            unsigned long long bk = 0xFFFFFFFFFFFFFFFFull;

            auto scan_range = [&](int c0, int c1) {   // linear cells [c0, c1] inclusive
                int s = cs[c0], e = cs[c1 + 1];
                for (int j = s; j < e; j++) {
                    float4 t = __ldg(&sp[j]);
                    float dx = px - t.x, dy = py - t.y, dz = pz - t.z;
                    float d2 = dx * dx;
                    d2 = __fmaf_rn(dy, dy, d2);
                    d2 = __fmaf_rn(dz, dz, d2);
                    unsigned long long kk =
                        ((unsigned long long)__float_as_uint(d2) << 32) |
                        (unsigned)__float_as_uint(t.w);
                    if (kk < bk) bk = kk;
                }
            };

            for (int k = 0; k < G; k++) {
                const int xl = max(cx - k, 0), xh = min(cx + k, G - 1);
                for (int dz = -k; dz <= k; dz++) {
                    const int iz = cz + dz;
                    if ((unsigned)iz >= (unsigned)G) continue;
                    const bool zf = (dz == -k) || (dz == k);
                    for (int dy = -k; dy <= k; dy++) {
                        const int iy = cy + dy;
                        if ((unsigned)iy >= (unsigned)G) continue;
                        const int cb = ((iz * G) + iy) * G;
                        if (zf || dy == -k || dy == k) {
                            scan_range(cb + xl, cb + xh);     // full contiguous row
                        } else {
                            if (cx - k >= 0) scan_range(cb + cx - k, cb + cx - k);
                            if (cx + k <= G - 1) scan_range(cb + cx + k, cb + cx + k);
                        }
                    }
                }
                if (k >= 1 && bk != 0xFFFFFFFFFFFFFFFFull) {
                    const float kd = CELL_H * (float)k - 1e-4f;
                    const float d2b = __uint_as_float((unsigned)(bk >> 32));
                    if (d2b <= kd * kd) break;   // unsearched shells strictly farther
                }
            }

            const int idx = (int)((unsigned)bk & (unsigned)(MPTS - 1));
            const float d2b = __uint_as_float((unsigned)(bk >> 32));
            const float dist = sqrtf(d2b);
            const float4 q = g_tgt4[(b << 12) + idx];

            v[0] = px; v[1] = py; v[2] = pz;
            v[3] = q.x; v[4] = q.y; v[5] = q.z;
            v[6] = px * q.x; v[7] = px * q.y; v[8] = px * q.z;
            v[9] = py * q.x; v[10] = py * q.y; v[11] = py * q.z;
            v[12] = pz * q.x; v[13] = pz * q.y; v[14] = pz * q.z;
            v[15] = dist;
        }

        // fixed-order deterministic block reduction (4 warps)
#pragma unroll
        for (int k = 0; k < 16; k++) {
            float a = v[k];
            a += __shfl_down_sync(0xffffffffu, a, 16);
            a += __shfl_down_sync(0xffffffffu, a, 8);
            a += __shfl_down_sync(0xffffffffu, a, 4);
            a += __shfl_down_sync(0xffffffffu, a, 2);
            a += __shfl_down_sync(0xffffffffu, a, 1);
            v[k] = a;
        }
        const int lane = tid & 31, warp = tid >> 5;
        if (lane == 0) {
#pragma unroll
            for (int k = 0; k < 16; k++) sm[warp][k] = v[k];
        }
        __syncthreads();
        if (tid < 16) {
            float a = sm[0][tid] + sm[1][tid] + sm[2][tid] + sm[3][tid];
            __stcg(&g_part[bx][tid], a);
        }
        __syncthreads();
        if (tid == 0) arrive(&g_tailcnt);
        return;
    }

    // =================== final block ===================
    {
        __shared__ float cRt[BATCH][12];
        __shared__ float c_S[BATCH][16];
        __shared__ float c_errnew[BATCH];
        __shared__ int c_done, c_done0;

        if (tid == 0) { wait_ge(&g_tailcnt, NN_BLKS); c_done0 = g_done; }
        __syncthreads();
        const int done0 = c_done0;

        if (tid < 24) {
            int bb = tid / 12, j = tid - bb * 12;
            cRt[bb][j] = (j < 9) ? g_Rcum[bb][j] : g_tcum[bb][j - 9];
        }
        __syncthreads();

        if (tid < 32) {
            const int bsel = tid >> 4, k = tid & 15;
            float a = 0.f;
#pragma unroll
            for (int c = 0; c < NCHB; c++)             // fixed order: deterministic
                a += __ldcg(&g_part[bsel * NCHB + c][k]);
            c_S[bsel][k] = a;
            if (k == 15) c_errnew[bsel] = a / (float)NPTS;
        }
        __syncthreads();

        if (tid == 0) {
            int conv = (fabsf(c_errnew[0] - g_err[0]) < TOLER) &&
                       (fabsf(c_errnew[1] - g_err[1]) < TOLER);
            c_done = (done0 || conv) ? 1 : 0;
            __stcg(&g_done, c_done);
        }
        __syncthreads();

        if (tid < BATCH && !c_done) {
            float S[16];
#pragma unroll
            for (int k = 0; k < 16; k++) S[k] = c_S[tid][k];
            float Rn[9], tn[3];
            solve_horn_f(S, Rn, tn);

            float Ro[9], to[3];
#pragma unroll
            for (int i = 0; i < 9; i++) Ro[i] = cRt[tid][i];
#pragma unroll
            for (int i = 0; i < 3; i++) to[i] = cRt[tid][9 + i];

#pragma unroll
            for (int i = 0; i < 3; i++) {
#pragma unroll
                for (int j = 0; j < 3; j++) {
                    float m = Rn[i * 3 + 0] * Ro[0 + j] + Rn[i * 3 + 1] * Ro[3 + j] +
                              Rn[i * 3 + 2] * Ro[6 + j];
                    __stcg(&g_Rcum[tid][i * 3 + j], m);
                }
                float tm = Rn[i * 3 + 0] * to[0] + Rn[i * 3 + 1] * to[1] +
                           Rn[i * 3 + 2] * to[2] + tn[i];
                __stcg(&g_tcum[tid][i], tm);
            }
            __stcg(&g_err[tid], c_errnew[tid]);
        }
        __syncthreads();

        if (tid == 0) __stcg(&g_tailcnt, 0u);   // re-arm for next step

        if (step == NSTEPS - 1 && tid < BATCH) {
            float R[9];
#pragma unroll
            for (int i = 0; i < 9; i++) R[i] = __ldcg(&g_Rcum[tid][i]);
            out[tid * 7 + 0] = __ldcg(&g_tcum[tid][0]);
            out[tid * 7 + 1] = __ldcg(&g_tcum[tid][1]);
            out[tid * 7 + 2] = __ldcg(&g_tcum[tid][2]);
            const float r00 = R[0], r11 = R[4], r22 = R[8];
            float qw = 0.5f * sqrtf(fmaxf(1.f + r00 + r11 + r22, 1e-12f));
            float qx = 0.5f * sqrtf(fmaxf(1.f + r00 - r11 - r22, 1e-12f));
            float qy = 0.5f * sqrtf(fmaxf(1.f - r00 + r11 - r22, 1e-12f));
            float qz = 0.5f * sqrtf(fmaxf(1.f - r00 - r11 + r22, 1e-12f));
            qx = (R[7] - R[5] >= 0.f) ? qx : -qx;
            qy = (R[2] - R[6] >= 0.f) ? qy : -qy;
            qz = (R[3] - R[1] >= 0.f) ? qz : -qz;
            out[tid * 7 + 3] = qx;
            out[tid * 7 + 4] = qy;
            out[tid * 7 + 5] = qz;
            out[tid * 7 + 6] = qw;
        }
    }
}

// ---------------- launch ----------------
extern "C" void kernel_launch(void* const* d_in, const int* in_sizes, int n_in,
                              void* d_out, int out_size) {
    const float* psrc = (const float*)d_in[0];
    const float* ptgt = (const float*)d_in[1];
    float* out = (float*)d_out;

    zero_kernel<<<1024, 256>>>();
    count_kernel<<<(BATCH * MPTS + 255) / 256, 256>>>(ptgt);
    scan_kernel<<<BATCH, 1024>>>();
    scatter_kernel<<<(BATCH * MPTS + 255) / 256, 256>>>(ptgt);

    for (int s = 0; s < NSTEPS; s++)
        step_kernel<<<TOTAL_BLKS, TPB>>>(psrc, out, s);
}

// round 13
// speedup vs baseline: 5.1940x; 5.1940x over previous
#include <cuda_runtime.h>
#include <math.h>

#define BATCH 2
#define NPTS 4096
#define MPTS 4096
#define NSTEPS 8
#define TOLER 1e-6f

#define TPB 1024                        // 32 warps per NN block
#define QPW 4                           // queries per warp
#define NCHB 32                         // 32 chunks of 128 queries per batch
#define NN_BLKS (BATCH * NCHB)          // 64
#define TOTAL_BLKS (NN_BLKS + 1)

// spatial grid over targets: 32^3 cells, h=0.5, covering [-8,8)
#define G 32
#define NC (G * G * G)
#define CELL_H 0.5f
#define INV_H 2.0f
#define GRID_LO 8.0f

// ---------------- device state ----------------
__device__ float4 g_tgt4[BATCH * MPTS];       // original targets (x,y,z,|t|^2)
__device__ float4 g_sorted[BATCH * MPTS];     // grid-sorted targets (x,y,z,idx-bits)
__device__ int g_cs[BATCH][NC + 1];           // cell start offsets (prefix)
__device__ int g_fill[BATCH][NC + 1];         // scatter cursors
__device__ unsigned g_cnt[BATCH][NC];         // per-cell counts
__device__ float g_Rcum[BATCH][9];
__device__ float g_tcum[BATCH][3];
__device__ float g_err[BATCH];
__device__ int g_done;
__device__ unsigned g_tailcnt;
__device__ float g_part[NN_BLKS][16];

__device__ __forceinline__ int cell_of(float v) {
    int c = (int)floorf((v + GRID_LO) * INV_H);
    return min(G - 1, max(0, c));
}

// ---------------- init chain ----------------
__global__ void zero_kernel() {
    int i = blockIdx.x * blockDim.x + threadIdx.x;
    for (int j = i; j < BATCH * NC; j += gridDim.x * blockDim.x)
        g_cnt[j / NC][j % NC] = 0u;
    if (i == 0) { g_done = 0; g_tailcnt = 0u; }
    if (i < BATCH) {
        g_err[i] = 0.0f;
        float* R = g_Rcum[i];
        R[0] = 1.f; R[1] = 0.f; R[2] = 0.f;
        R[3] = 0.f; R[4] = 1.f; R[5] = 0.f;
        R[6] = 0.f; R[7] = 0.f; R[8] = 1.f;
        g_tcum[i][0] = 0.f; g_tcum[i][1] = 0.f; g_tcum[i][2] = 0.f;
    }
}

__global__ void count_kernel(const float* __restrict__ ptgt) {
    int i = blockIdx.x * blockDim.x + threadIdx.x;   // 0..8191
    if (i >= BATCH * MPTS) return;
    float x = ptgt[i * 3 + 0];
    float y = ptgt[i * 3 + 1];
    float z = ptgt[i * 3 + 2];
    g_tgt4[i] = make_float4(x, y, z, x * x + y * y + z * z);
    int c = (cell_of(z) * G + cell_of(y)) * G + cell_of(x);
    atomicAdd(&g_cnt[i >> 12][c], 1u);
}

__global__ __launch_bounds__(1024) void scan_kernel() {
    const int b = blockIdx.x;
    const int t = threadIdx.x;
    const int CH = NC / 1024;            // 32 cells per thread
    const int base = t * CH;

    unsigned sum = 0;
    for (int i = 0; i < CH; i++) sum += g_cnt[b][base + i];

    __shared__ unsigned a[1024];
    a[t] = sum;
    __syncthreads();
    for (int off = 1; off < 1024; off <<= 1) {
        unsigned v = (t >= off) ? a[t - off] : 0u;
        __syncthreads();
        a[t] += v;
        __syncthreads();
    }
    unsigned run = a[t] - sum;           // exclusive prefix

    for (int i = 0; i < CH; i++) {
        unsigned c = g_cnt[b][base + i];
        g_cs[b][base + i] = (int)run;
        g_fill[b][base + i] = (int)run;
        run += c;
    }
    if (t == 1023) g_cs[b][NC] = (int)run;   // == MPTS
}

__global__ void scatter_kernel(const float* __restrict__ ptgt) {
    int i = blockIdx.x * blockDim.x + threadIdx.x;
    if (i >= BATCH * MPTS) return;
    const int b = i >> 12;
    float x = ptgt[i * 3 + 0];
    float y = ptgt[i * 3 + 1];
    float z = ptgt[i * 3 + 2];
    int c = (cell_of(z) * G + cell_of(y)) * G + cell_of(x);
    int pos = atomicAdd(&g_fill[b][c], 1);
    g_sorted[(b << 12) + pos] = make_float4(x, y, z, __uint_as_float((unsigned)(i & (MPTS - 1))));
}

// ---------------- float Horn quaternion Kabsch ----------------
__device__ __forceinline__ void matmul4(float* C, const float* A, const float* Bm) {
#pragma unroll
    for (int i = 0; i < 4; i++)
#pragma unroll
        for (int j = 0; j < 4; j++) {
            float a = 0.f;
#pragma unroll
            for (int k = 0; k < 4; k++) a = __fmaf_rn(A[i * 4 + k], Bm[k * 4 + j], a);
            C[i * 4 + j] = a;
        }
}

__device__ void solve_horn_f(const float* S, float* Rn, float* tn) {
    const float n = (float)NPTS;
    const float inv = 1.0f / n;
    const float pmx = S[0] * inv, pmy = S[1] * inv, pmz = S[2] * inv;
    const float qmx = S[3] * inv, qmy = S[4] * inv, qmz = S[5] * inv;

    const float Sxx = S[6]  - n * pmx * qmx, Sxy = S[7]  - n * pmx * qmy, Sxz = S[8]  - n * pmx * qmz;
    const float Syx = S[9]  - n * pmy * qmx, Syy = S[10] - n * pmy * qmy, Syz = S[11] - n * pmy * qmz;
    const float Szx = S[12] - n * pmz * qmx, Szy = S[13] - n * pmz * qmy, Szz = S[14] - n * pmz * qmz;

    float K[16];
    K[0]  = Sxx + Syy + Szz; K[1]  = Syz - Szy;        K[2]  = Szx - Sxz;       K[3]  = Sxy - Syx;
    K[5]  = Sxx - Syy - Szz; K[6]  = Sxy + Syx;        K[7]  = Szx + Sxz;
    K[10] = -Sxx + Syy - Szz; K[11] = Syz + Szy;
    K[15] = -Sxx - Syy + Szz;
    K[4] = K[1]; K[8] = K[2]; K[12] = K[3]; K[9] = K[6]; K[13] = K[7]; K[14] = K[11];

    float fro = 0.f;
#pragma unroll
    for (int i = 0; i < 16; i++) fro += K[i] * K[i];
    const float sc = rsqrtf(fro + 1e-30f);

    float Kf[16];
#pragma unroll
    for (int i = 0; i < 16; i++) Kf[i] = K[i] * sc;
    Kf[0] += 1.f; Kf[5] += 1.f; Kf[10] += 1.f; Kf[15] += 1.f;  // eigs in [0,2]

    float K2[16], K4[16];
    matmul4(K2, Kf, Kf);
    matmul4(K4, K2, K2);

    float v0 = 1.f, v1 = 0.02f, v2 = 0.03f, v3 = 0.04f;
#pragma unroll 4
    for (int it = 0; it < 48; it++) {
        float w0 = K4[0]  * v0 + K4[1]  * v1 + K4[2]  * v2 + K4[3]  * v3;
        float w1 = K4[4]  * v0 + K4[5]  * v1 + K4[6]  * v2 + K4[7]  * v3;
        float w2 = K4[8]  * v0 + K4[9]  * v1 + K4[10] * v2 + K4[11] * v3;
        float w3 = K4[12] * v0 + K4[13] * v1 + K4[14] * v2 + K4[15] * v3;
        if ((it & 3) == 3) {
            float r = rsqrtf(w0 * w0 + w1 * w1 + w2 * w2 + w3 * w3 + 1e-30f);
            w0 *= r; w1 *= r; w2 *= r; w3 *= r;
        }
        v0 = w0; v1 = w1; v2 = w2; v3 = w3;
    }

    const float qw = v0, qx = v1, qy = v2, qz = v3;
    const float nn = qw * qw + qx * qx + qy * qy + qz * qz;
    const float s2 = 2.0f / nn;
    Rn[0] = 1.f - s2 * (qy * qy + qz * qz); Rn[1] = s2 * (qx * qy - qw * qz); Rn[2] = s2 * (qx * qz + qw * qy);
    Rn[3] = s2 * (qx * qy + qw * qz); Rn[4] = 1.f - s2 * (qx * qx + qz * qz); Rn[5] = s2 * (qy * qz - qw * qx);
    Rn[6] = s2 * (qx * qz - qw * qy); Rn[7] = s2 * (qy * qz + qw * qx); Rn[8] = 1.f - s2 * (qx * qx + qy * qy);

    tn[0] = qmx - (Rn[0] * pmx + Rn[1] * pmy + Rn[2] * pmz);
    tn[1] = qmy - (Rn[3] * pmx + Rn[4] * pmy + Rn[5] * pmz);
    tn[2] = qmz - (Rn[6] * pmx + Rn[7] * pmy + Rn[8] * pmz);
}

// ---------------- sync helpers ----------------
__device__ __forceinline__ void arrive(unsigned* p) {
    unsigned old;
    asm volatile("atom.acq_rel.gpu.global.add.u32 %0, [%1], %2;"
                 : "=r"(old) : "l"(p), "r"(1u) : "memory");
}
__device__ __forceinline__ void wait_ge(unsigned* p, unsigned target) {
    unsigned v;
    for (;;) {
        asm volatile("ld.acquire.gpu.global.u32 %0, [%1];"
                     : "=r"(v) : "l"(p) : "memory");
        if (v >= target) break;
        __nanosleep(32);
    }
}

// ---------------- one ICP step: warp-coop grid-NN + reduce -> final solve ----------------
__global__ __launch_bounds__(TPB) void step_kernel(const float* __restrict__ psrc,
                                                   float* __restrict__ out, int step) {
    const int tid = threadIdx.x;
    const int bx = blockIdx.x;

    // =================== NN + reduce blocks (32 warps, 4 queries/warp) ==========
    if (bx < NN_BLKS) {
        __shared__ float sRt[12];
        __shared__ int sdone;
        __shared__ float sm[32][16];

        const int b = bx >> 5;
        const int chunk = bx & 31;
        const int lane = tid & 31;
        const int w = tid >> 5;

        if (tid < 12)
            sRt[tid] = (tid < 9) ? g_Rcum[b][tid] : g_tcum[b][tid - 9];
        if (tid == 0) sdone = g_done;
        __syncthreads();

        float acc[16];
#pragma unroll
        for (int k = 0; k < 16; k++) acc[k] = 0.f;

        if (!sdone) {
            const float R0 = sRt[0], R1 = sRt[1], R2 = sRt[2];
            const float R3 = sRt[3], R4 = sRt[4], R5 = sRt[5];
            const float R6 = sRt[6], R7 = sRt[7], R8 = sRt[8];
            const float t0 = sRt[9], t1 = sRt[10], t2 = sRt[11];
            const int* cs = g_cs[b];
            const float4* sp = g_sorted + (b << 12);

            for (int qi = 0; qi < QPW; qi++) {
                const int n = chunk * 128 + w * QPW + qi;
                const float* ps = psrc + ((size_t)b * NPTS + n) * 3;
                const float x = ps[0], y = ps[1], z = ps[2];
                const float px = R0 * x + R1 * y + R2 * z + t0;
                const float py = R3 * x + R4 * y + R5 * z + t1;
                const float pz = R6 * x + R7 * y + R8 * z + t2;

                const int cx = cell_of(px), cy = cell_of(py), cz = cell_of(pz);
                unsigned long long bk = 0xFFFFFFFFFFFFFFFFull;

                for (int k = 1; k < G; k++) {
                    const int d = 2 * k + 1;
                    const int nrows = d * d;
                    const int xl = max(cx - k, 0), xh = min(cx + k, G - 1);

                    for (int rb = 0; rb < nrows; rb += 32) {
                        int s = 0, e = 0;
                        const int r = rb + lane;
                        if (r < nrows) {
                            const int iz = cz + r / d - k;
                            const int iy = cy + r % d - k;
                            if ((unsigned)iz < (unsigned)G && (unsigned)iy < (unsigned)G) {
                                const int cb = (iz * G + iy) * G;
                                s = cs[cb + xl];
                                e = cs[cb + xh + 1];
                            }
                        }
                        const int cnt = min(32, nrows - rb);
                        for (int rr = 0; rr < cnt; rr++) {
                            const int ss = __shfl_sync(0xffffffffu, s, rr);
                            const int ee = __shfl_sync(0xffffffffu, e, rr);
                            for (int j = ss + lane; j < ee; j += 32) {
                                const float4 t = __ldg(&sp[j]);
                                float dx = px - t.x, dy = py - t.y, dz = pz - t.z;
                                float d2 = dx * dx;
                                d2 = __fmaf_rn(dy, dy, d2);
                                d2 = __fmaf_rn(dz, dz, d2);
                                unsigned long long kk =
                                    ((unsigned long long)__float_as_uint(d2) << 32) |
                                    (unsigned)__float_as_uint(t.w);
                                if (kk < bk) bk = kk;
                            }
                        }
                    }

                    // warp-reduce min and test shell bound
                    unsigned long long m = bk;
#pragma unroll
                    for (int off = 16; off >= 1; off >>= 1) {
                        unsigned long long o = __shfl_xor_sync(0xffffffffu, m, off);
                        if (o < m) m = o;
                    }
                    bk = m;
                    const float d2b = __uint_as_float((unsigned)(m >> 32));
                    const float kd = CELL_H * (float)k - 1e-4f;
                    if (d2b <= kd * kd) break;   // unsearched shells strictly farther
                }

                if (lane == 0) {
                    const int idx = (int)((unsigned)bk & (unsigned)(MPTS - 1));
                    const float d2b = __uint_as_float((unsigned)(bk >> 32));
                    const float dist = sqrtf(d2b);
                    const float4 q = g_tgt4[(b << 12) + idx];
                    acc[0] += px; acc[1] += py; acc[2] += pz;
                    acc[3] += q.x; acc[4] += q.y; acc[5] += q.z;
                    acc[6] += px * q.x; acc[7] += px * q.y; acc[8] += px * q.z;
                    acc[9] += py * q.x; acc[10] += py * q.y; acc[11] += py * q.z;
                    acc[12] += pz * q.x; acc[13] += pz * q.y; acc[14] += pz * q.z;
                    acc[15] += dist;
                }
            }
        }

        // block reduce: lane 0 of each warp -> smem -> fixed-order sum over 32 warps
        if (lane == 0) {
#pragma unroll
            for (int k = 0; k < 16; k++) sm[w][k] = acc[k];
        }
        __syncthreads();
        if (tid < 16) {
            float a = 0.f;
#pragma unroll
            for (int ww = 0; ww < 32; ww++) a += sm[ww][tid];   // fixed order
            __stcg(&g_part[bx][tid], a);
        }
        __syncthreads();
        if (tid == 0) arrive(&g_tailcnt);
        return;
    }

    // =================== final block ===================
    {
        __shared__ float cRt[BATCH][12];
        __shared__ float c_S[BATCH][16];
        __shared__ float c_errnew[BATCH];
        __shared__ int c_done, c_done0;

        if (tid == 0) { wait_ge(&g_tailcnt, NN_BLKS); c_done0 = g_done; }
        __syncthreads();
        const int done0 = c_done0;

        if (tid < 24) {
            int bb = tid / 12, j = tid - bb * 12;
            cRt[bb][j] = (j < 9) ? g_Rcum[bb][j] : g_tcum[bb][j - 9];
        }
        __syncthreads();

        if (tid < 32) {
            const int bsel = tid >> 4, k = tid & 15;
            float a = 0.f;
#pragma unroll
            for (int c = 0; c < NCHB; c++)             // fixed order: deterministic
                a += __ldcg(&g_part[bsel * NCHB + c][k]);
            c_S[bsel][k] = a;
            if (k == 15) c_errnew[bsel] = a / (float)NPTS;
        }
        __syncthreads();

        if (tid == 0) {
            int conv = (fabsf(c_errnew[0] - g_err[0]) < TOLER) &&
                       (fabsf(c_errnew[1] - g_err[1]) < TOLER);
            c_done = (done0 || conv) ? 1 : 0;
            __stcg(&g_done, c_done);
        }
        __syncthreads();

        if (tid < BATCH && !c_done) {
            float S[16];
#pragma unroll
            for (int k = 0; k < 16; k++) S[k] = c_S[tid][k];
            float Rn[9], tn[3];
            solve_horn_f(S, Rn, tn);

            float Ro[9], to[3];
#pragma unroll
            for (int i = 0; i < 9; i++) Ro[i] = cRt[tid][i];
#pragma unroll
            for (int i = 0; i < 3; i++) to[i] = cRt[tid][9 + i];

#pragma unroll
            for (int i = 0; i < 3; i++) {
#pragma unroll
                for (int j = 0; j < 3; j++) {
                    float m = Rn[i * 3 + 0] * Ro[0 + j] + Rn[i * 3 + 1] * Ro[3 + j] +
                              Rn[i * 3 + 2] * Ro[6 + j];
                    __stcg(&g_Rcum[tid][i * 3 + j], m);
                }
                float tm = Rn[i * 3 + 0] * to[0] + Rn[i * 3 + 1] * to[1] +
                           Rn[i * 3 + 2] * to[2] + tn[i];
                __stcg(&g_tcum[tid][i], tm);
            }
            __stcg(&g_err[tid], c_errnew[tid]);
        }
        __syncthreads();

        if (tid == 0) __stcg(&g_tailcnt, 0u);   // re-arm for next step

        if (step == NSTEPS - 1 && tid < BATCH) {
            float R[9];
#pragma unroll
            for (int i = 0; i < 9; i++) R[i] = __ldcg(&g_Rcum[tid][i]);
            out[tid * 7 + 0] = __ldcg(&g_tcum[tid][0]);
            out[tid * 7 + 1] = __ldcg(&g_tcum[tid][1]);
            out[tid * 7 + 2] = __ldcg(&g_tcum[tid][2]);
            const float r00 = R[0], r11 = R[4], r22 = R[8];
            float qw = 0.5f * sqrtf(fmaxf(1.f + r00 + r11 + r22, 1e-12f));
            float qx = 0.5f * sqrtf(fmaxf(1.f + r00 - r11 - r22, 1e-12f));
            float qy = 0.5f * sqrtf(fmaxf(1.f - r00 + r11 - r22, 1e-12f));
            float qz = 0.5f * sqrtf(fmaxf(1.f - r00 - r11 + r22, 1e-12f));
            qx = (R[7] - R[5] >= 0.f) ? qx : -qx;
            qy = (R[2] - R[6] >= 0.f) ? qy : -qy;
            qz = (R[3] - R[1] >= 0.f) ? qz : -qz;
            out[tid * 7 + 3] = qx;
            out[tid * 7 + 4] = qy;
            out[tid * 7 + 5] = qz;
            out[tid * 7 + 6] = qw;
        }
    }
}

// ---------------- launch ----------------
extern "C" void kernel_launch(void* const* d_in, const int* in_sizes, int n_in,
                              void* d_out, int out_size) {
    const float* psrc = (const float*)d_in[0];
    const float* ptgt = (const float*)d_in[1];
    float* out = (float*)d_out;

    zero_kernel<<<256, 256>>>();
    count_kernel<<<(BATCH * MPTS + 255) / 256, 256>>>(ptgt);
    scan_kernel<<<BATCH, 1024>>>();
    scatter_kernel<<<(BATCH * MPTS + 255) / 256, 256>>>(ptgt);

    for (int s = 0; s < NSTEPS; s++)
        step_kernel<<<TOTAL_BLKS, TPB>>>(psrc, out, s);
}

// round 14
// speedup vs baseline: 11.1931x; 2.1550x over previous
#include <cuda_runtime.h>
#include <math.h>

#define BATCH 2
#define NPTS 4096
#define MPTS 4096
#define NSTEPS 8
#define TOLER 1e-6f

#define TPB 128
#define MSPLIT 32
#define MCH 128                         // targets per nn tile (== TPB)
#define NCHB 16                         // chunks of 256 queries per batch
#define QCH 256                         // queries per chunk (2 per thread)
#define NN_BLKS (BATCH * NCHB * MSPLIT) // 1024
#define TAIL_BLKS 64                    // one per 128 points
#define NCNT (BATCH * NCHB)             // 32 producer counters
#define TOTAL_BLKS (NN_BLKS + TAIL_BLKS + 1)

// ---------------- device state ----------------
__device__ float4 g_tgt4[BATCH * MPTS];             // (x,y,z,|t|^2)
__device__ unsigned long long g_scr[BATCH * NPTS];  // packed (orderable score | idx)
__device__ float g_Rcum[BATCH][9];
__device__ float g_tcum[BATCH][3];
__device__ float g_err[BATCH];
__device__ int g_done;
__device__ unsigned g_cnt[NCNT * 32];               // per-(b,chunk) counters, 128B apart
__device__ unsigned g_tailcnt;
__device__ float g_part[TAIL_BLKS][16];

// ---------------- init ----------------
__global__ void init_kernel(const float* __restrict__ ptgt) {
    int i = blockIdx.x * blockDim.x + threadIdx.x;  // 0..8191
    if (i < BATCH * MPTS) {
        float x = ptgt[i * 3 + 0];
        float y = ptgt[i * 3 + 1];
        float z = ptgt[i * 3 + 2];
        g_tgt4[i] = make_float4(x, y, z, x * x + y * y + z * z);
        g_scr[i] = 0xFFFFFFFFFFFFFFFFull;
    }
    if (i < NCNT * 32) g_cnt[i] = 0u;
    if (i == 0) { g_done = 0; g_tailcnt = 0u; }
    if (i < BATCH) {
        g_err[i] = 0.0f;
        float* R = g_Rcum[i];
        R[0] = 1.f; R[1] = 0.f; R[2] = 0.f;
        R[3] = 0.f; R[4] = 1.f; R[5] = 0.f;
        R[6] = 0.f; R[7] = 0.f; R[8] = 1.f;
        g_tcum[i][0] = 0.f; g_tcum[i][1] = 0.f; g_tcum[i][2] = 0.f;
    }
}

// ---------------- float Horn quaternion Kabsch ----------------
__device__ __forceinline__ void matmul4(float* C, const float* A, const float* Bm) {
#pragma unroll
    for (int i = 0; i < 4; i++)
#pragma unroll
        for (int j = 0; j < 4; j++) {
            float a = 0.f;
#pragma unroll
            for (int k = 0; k < 4; k++) a = __fmaf_rn(A[i * 4 + k], Bm[k * 4 + j], a);
            C[i * 4 + j] = a;
        }
}

__device__ void solve_horn_f(const float* S, float* Rn, float* tn) {
    const float n = (float)NPTS;
    const float inv = 1.0f / n;
    const float pmx = S[0] * inv, pmy = S[1] * inv, pmz = S[2] * inv;
    const float qmx = S[3] * inv, qmy = S[4] * inv, qmz = S[5] * inv;

    const float Sxx = S[6]  - n * pmx * qmx, Sxy = S[7]  - n * pmx * qmy, Sxz = S[8]  - n * pmx * qmz;
    const float Syx = S[9]  - n * pmy * qmx, Syy = S[10] - n * pmy * qmy, Syz = S[11] - n * pmy * qmz;
    const float Szx = S[12] - n * pmz * qmx, Szy = S[13] - n * pmz * qmy, Szz = S[14] - n * pmz * qmz;

    float K[16];
    K[0]  = Sxx + Syy + Szz; K[1]  = Syz - Szy;        K[2]  = Szx - Sxz;       K[3]  = Sxy - Syx;
    K[5]  = Sxx - Syy - Szz; K[6]  = Sxy + Syx;        K[7]  = Szx + Sxz;
    K[10] = -Sxx + Syy - Szz; K[11] = Syz + Szy;
    K[15] = -Sxx - Syy + Szz;
    K[4] = K[1]; K[8] = K[2]; K[12] = K[3]; K[9] = K[6]; K[13] = K[7]; K[14] = K[11];

    float fro = 0.f;
#pragma unroll
    for (int i = 0; i < 16; i++) fro += K[i] * K[i];
    const float sc = rsqrtf(fro + 1e-30f);

    float Kf[16];
#pragma unroll
    for (int i = 0; i < 16; i++) Kf[i] = K[i] * sc;
    Kf[0] += 1.f; Kf[5] += 1.f; Kf[10] += 1.f; Kf[15] += 1.f;  // eigs in [0,2]

    float K2[16], K4[16];
    matmul4(K2, Kf, Kf);
    matmul4(K4, K2, K2);

    float v0 = 1.f, v1 = 0.02f, v2 = 0.03f, v3 = 0.04f;
#pragma unroll 4
    for (int it = 0; it < 48; it++) {
        float w0 = K4[0]  * v0 + K4[1]  * v1 + K4[2]  * v2 + K4[3]  * v3;
        float w1 = K4[4]  * v0 + K4[5]  * v1 + K4[6]  * v2 + K4[7]  * v3;
        float w2 = K4[8]  * v0 + K4[9]  * v1 + K4[10] * v2 + K4[11] * v3;
        float w3 = K4[12] * v0 + K4[13] * v1 + K4[14] * v2 + K4[15] * v3;
        if ((it & 3) == 3) {
            float r = rsqrtf(w0 * w0 + w1 * w1 + w2 * w2 + w3 * w3 + 1e-30f);
            w0 *= r; w1 *= r; w2 *= r; w3 *= r;
        }
        v0 = w0; v1 = w1; v2 = w2; v3 = w3;
    }

    const float qw = v0, qx = v1, qy = v2, qz = v3;
    const float nn = qw * qw + qx * qx + qy * qy + qz * qz;
    const float s2 = 2.0f / nn;
    Rn[0] = 1.f - s2 * (qy * qy + qz * qz); Rn[1] = s2 * (qx * qy - qw * qz); Rn[2] = s2 * (qx * qz + qw * qy);
    Rn[3] = s2 * (qx * qy + qw * qz); Rn[4] = 1.f - s2 * (qx * qx + qz * qz); Rn[5] = s2 * (qy * qz - qw * qx);
    Rn[6] = s2 * (qx * qz - qw * qy); Rn[7] = s2 * (qy * qz + qw * qx); Rn[8] = 1.f - s2 * (qx * qx + qy * qy);

    tn[0] = qmx - (Rn[0] * pmx + Rn[1] * pmy + Rn[2] * pmz);
    tn[1] = qmy - (Rn[3] * pmx + Rn[4] * pmy + Rn[5] * pmz);
    tn[2] = qmz - (Rn[6] * pmx + Rn[7] * pmy + Rn[8] * pmz);
}

// ---------------- sync helpers ----------------
__device__ __forceinline__ void arrive(unsigned* p) {
    unsigned old;
    asm volatile("atom.acq_rel.gpu.global.add.u32 %0, [%1], %2;"
                 : "=r"(old) : "l"(p), "r"(1u) : "memory");
}
__device__ __forceinline__ void wait_ge(unsigned* p, unsigned target) {
    unsigned v;
    for (;;) {
        asm volatile("ld.acquire.gpu.global.u32 %0, [%1];"
                     : "=r"(v) : "l"(p) : "memory");
        if (v >= target) break;
        __nanosleep(32);
    }
}

// ---------------- one ICP step: NN (ILP-2) -> tail reduce -> final solve ----------------
__global__ __launch_bounds__(TPB, 8) void step_kernel(const float* __restrict__ psrc,
                                                      float* __restrict__ out, int step) {
    const int tid = threadIdx.x;
    const int bx = blockIdx.x;

    // =================== NN blocks (2 queries per thread) ===================
    if (bx < NN_BLKS) {
        __shared__ float4 sh[MCH];
        __shared__ float sRt[12];
        __shared__ int sdone;

        const int b = bx >> 9;                  // 512 blocks per batch
        const int mtile = bx & 31;
        const int nchunk = (bx >> 5) & 15;
        const int mbase = mtile * MCH;
        const int n0 = nchunk * QCH + tid;
        const int n1 = n0 + TPB;

        if (tid < 12)
            sRt[tid] = (tid < 9) ? g_Rcum[b][tid] : g_tcum[b][tid - 9];
        if (tid == 0) sdone = g_done;
        sh[tid] = g_tgt4[b * MPTS + mbase + tid];
        __syncthreads();

        if (!sdone) {
            const float R0 = sRt[0], R1 = sRt[1], R2 = sRt[2];
            const float R3 = sRt[3], R4 = sRt[4], R5 = sRt[5];
            const float R6 = sRt[6], R7 = sRt[7], R8 = sRt[8];
            const float t0 = sRt[9], t1 = sRt[10], t2 = sRt[11];

            const float* p0 = psrc + ((size_t)b * NPTS + n0) * 3;
            const float* p1 = psrc + ((size_t)b * NPTS + n1) * 3;
            const float x0 = p0[0], y0 = p0[1], z0 = p0[2];
            const float x1 = p1[0], y1 = p1[1], z1 = p1[2];

            const float px0 = R0 * x0 + R1 * y0 + R2 * z0 + t0;
            const float py0 = R3 * x0 + R4 * y0 + R5 * z0 + t1;
            const float pz0 = R6 * x0 + R7 * y0 + R8 * z0 + t2;
            const float px1 = R0 * x1 + R1 * y1 + R2 * z1 + t0;
            const float py1 = R3 * x1 + R4 * y1 + R5 * z1 + t1;
            const float pz1 = R6 * x1 + R7 * y1 + R8 * z1 + t2;
            const float ax0 = -2.f * px0, ay0 = -2.f * py0, az0 = -2.f * pz0;
            const float ax1 = -2.f * px1, ay1 = -2.f * py1, az1 = -2.f * pz1;

            float bs0 = 3.0e38f, bs1 = 3.0e38f;
            int bi0 = 0, bi1 = 0;
#pragma unroll 8
            for (int m = 0; m < MCH; m++) {
                const float4 t = sh[m];       // warp-uniform broadcast, amortized 2x
                float s0 = __fmaf_rn(ax0, t.x, t.w);
                s0 = __fmaf_rn(ay0, t.y, s0);
                s0 = __fmaf_rn(az0, t.z, s0);
                float s1 = __fmaf_rn(ax1, t.x, t.w);
                s1 = __fmaf_rn(ay1, t.y, s1);
                s1 = __fmaf_rn(az1, t.z, s1);
                if (s0 < bs0) { bs0 = s0; bi0 = m; }
                if (s1 < bs1) { bs1 = s1; bi1 = m; }
            }

            unsigned u0 = __float_as_uint(bs0);
            u0 = (u0 & 0x80000000u) ? ~u0 : (u0 | 0x80000000u);
            unsigned u1 = __float_as_uint(bs1);
            u1 = (u1 & 0x80000000u) ? ~u1 : (u1 | 0x80000000u);
            atomicMin(g_scr + (size_t)b * NPTS + n0,
                      ((unsigned long long)u0 << 32) | (unsigned)(mbase + bi0));
            atomicMin(g_scr + (size_t)b * NPTS + n1,
                      ((unsigned long long)u1 << 32) | (unsigned)(mbase + bi1));
        }
        __syncthreads();
        if (tid == 0) arrive(&g_cnt[(b * NCHB + nchunk) * 32]);
        return;
    }

    // =================== tail blocks (one per 128 points) ===================
    if (bx < NN_BLKS + TAIL_BLKS) {
        __shared__ float sRt[12];
        __shared__ int sdone;
        __shared__ float sm[4][16];

        const int t = bx - NN_BLKS;
        const int b = t >> 5;
        const int seg = t & 31;            // 128-point segment within batch
        const int chunk = seg >> 1;        // producer chunk (256 points)

        if (tid == 0) wait_ge(&g_cnt[(b * NCHB + chunk) * 32], MSPLIT);
        if (tid < 12)
            sRt[tid] = (tid < 9) ? g_Rcum[b][tid] : g_tcum[b][tid - 9];
        if (tid == 0) sdone = g_done;
        __syncthreads();

        const int p = b * NPTS + seg * TPB + tid;
        float v[16];
#pragma unroll
        for (int k = 0; k < 16; k++) v[k] = 0.f;

        const unsigned long long key = __ldcg(&g_scr[p]);
        __stcg(&g_scr[p], 0xFFFFFFFFFFFFFFFFull);   // re-arm for next step

        if (!sdone) {
            unsigned u = (unsigned)(key >> 32);
            unsigned fb = (u & 0x80000000u) ? (u ^ 0x80000000u) : ~u;
            const float s = __uint_as_float(fb);
            const int idx = ((int)(unsigned)(key & 0xFFFFFFFFull)) & (MPTS - 1);
            const float4 q = g_tgt4[(b << 12) + idx];

            const float* ps = psrc + (size_t)p * 3;
            const float x = ps[0], y = ps[1], z = ps[2];
            const float R0 = sRt[0], R1 = sRt[1], R2 = sRt[2];
            const float R3 = sRt[3], R4 = sRt[4], R5 = sRt[5];
            const float R6 = sRt[6], R7 = sRt[7], R8 = sRt[8];
            const float px = R0 * x + R1 * y + R2 * z + sRt[9];
            const float py = R3 * x + R4 * y + R5 * z + sRt[10];
            const float pz = R6 * x + R7 * y + R8 * z + sRt[11];
            const float pn = px * px + py * py + pz * pz;
            const float dist = sqrtf(fmaxf(pn + s, 0.0f));

            v[0] = px; v[1] = py; v[2] = pz;
            v[3] = q.x; v[4] = q.y; v[5] = q.z;
            v[6] = px * q.x; v[7] = px * q.y; v[8] = px * q.z;
            v[9] = py * q.x; v[10] = py * q.y; v[11] = py * q.z;
            v[12] = pz * q.x; v[13] = pz * q.y; v[14] = pz * q.z;
            v[15] = dist;
        }

        // fixed-order deterministic block reduction (4 warps)
#pragma unroll
        for (int k = 0; k < 16; k++) {
            float a = v[k];
            a += __shfl_down_sync(0xffffffffu, a, 16);
            a += __shfl_down_sync(0xffffffffu, a, 8);
            a += __shfl_down_sync(0xffffffffu, a, 4);
            a += __shfl_down_sync(0xffffffffu, a, 2);
            a += __shfl_down_sync(0xffffffffu, a, 1);
            v[k] = a;
        }
        const int lane = tid & 31, warp = tid >> 5;
        if (lane == 0) {
#pragma unroll
            for (int k = 0; k < 16; k++) sm[warp][k] = v[k];
        }
        __syncthreads();
        if (tid < 16) {
            float a = sm[0][tid] + sm[1][tid] + sm[2][tid] + sm[3][tid];
            __stcg(&g_part[t][tid], a);
        }
        __syncthreads();
        if (tid == 0) arrive(&g_tailcnt);
        return;
    }

    // =================== final block ===================
    {
        __shared__ float cRt[BATCH][12];
        __shared__ float c_S[BATCH][16];
        __shared__ float c_errnew[BATCH];
        __shared__ int c_done, c_done0;

        if (tid == 0) { wait_ge(&g_tailcnt, TAIL_BLKS); c_done0 = g_done; }
        __syncthreads();
        const int done0 = c_done0;

        if (tid < 24) {
            int bb = tid / 12, j = tid - bb * 12;
            cRt[bb][j] = (j < 9) ? g_Rcum[bb][j] : g_tcum[bb][j - 9];
        }
        __syncthreads();

        if (tid < 32) {
            const int bsel = tid >> 4, k = tid & 15;
            float a = 0.f;
#pragma unroll
            for (int c = 0; c < 32; c++)               // fixed order: deterministic
                a += __ldcg(&g_part[bsel * 32 + c][k]);
            c_S[bsel][k] = a;
            if (k == 15) c_errnew[bsel] = a / (float)NPTS;
        }
        __syncthreads();

        if (tid == 0) {
            int conv = (fabsf(c_errnew[0] - g_err[0]) < TOLER) &&
                       (fabsf(c_errnew[1] - g_err[1]) < TOLER);
            c_done = (done0 || conv) ? 1 : 0;
            __stcg(&g_done, c_done);
        }
        __syncthreads();

        if (tid < BATCH && !c_done) {
            float S[16];
#pragma unroll
            for (int k = 0; k < 16; k++) S[k] = c_S[tid][k];
            float Rn[9], tn[3];
            solve_horn_f(S, Rn, tn);

            float Ro[9], to[3];
#pragma unroll
            for (int i = 0; i < 9; i++) Ro[i] = cRt[tid][i];
#pragma unroll
            for (int i = 0; i < 3; i++) to[i] = cRt[tid][9 + i];

#pragma unroll
            for (int i = 0; i < 3; i++) {
#pragma unroll
                for (int j = 0; j < 3; j++) {
                    float m = Rn[i * 3 + 0] * Ro[0 + j] + Rn[i * 3 + 1] * Ro[3 + j] +
                              Rn[i * 3 + 2] * Ro[6 + j];
                    __stcg(&g_Rcum[tid][i * 3 + j], m);
                }
                float tm = Rn[i * 3 + 0] * to[0] + Rn[i * 3 + 1] * to[1] +
                           Rn[i * 3 + 2] * to[2] + tn[i];
                __stcg(&g_tcum[tid][i], tm);
            }
            __stcg(&g_err[tid], c_errnew[tid]);
        }
        __syncthreads();

        // reset counters for next step kernel
        for (int i = tid; i < NCNT * 32; i += TPB) __stcg(&g_cnt[i], 0u);
        if (tid == 0) __stcg(&g_tailcnt, 0u);

        if (step == NSTEPS - 1 && tid < BATCH) {
            float R[9];
#pragma unroll
            for (int i = 0; i < 9; i++) R[i] = __ldcg(&g_Rcum[tid][i]);
            out[tid * 7 + 0] = __ldcg(&g_tcum[tid][0]);
            out[tid * 7 + 1] = __ldcg(&g_tcum[tid][1]);
            out[tid * 7 + 2] = __ldcg(&g_tcum[tid][2]);
            const float r00 = R[0], r11 = R[4], r22 = R[8];
            float qw = 0.5f * sqrtf(fmaxf(1.f + r00 + r11 + r22, 1e-12f));
            float qx = 0.5f * sqrtf(fmaxf(1.f + r00 - r11 - r22, 1e-12f));
            float qy = 0.5f * sqrtf(fmaxf(1.f - r00 + r11 - r22, 1e-12f));
            float qz = 0.5f * sqrtf(fmaxf(1.f - r00 - r11 + r22, 1e-12f));
            qx = (R[7] - R[5] >= 0.f) ? qx : -qx;
            qy = (R[2] - R[6] >= 0.f) ? qy : -qy;
            qz = (R[3] - R[1] >= 0.f) ? qz : -qz;
            out[tid * 7 + 3] = qx;
            out[tid * 7 + 4] = qy;
            out[tid * 7 + 5] = qz;
            out[tid * 7 + 6] = qw;
        }
    }
}

// ---------------- launch ----------------
extern "C" void kernel_launch(void* const* d_in, const int* in_sizes, int n_in,
                              void* d_out, int out_size) {
    const float* psrc = (const float*)d_in[0];
    const float* ptgt = (const float*)d_in[1];
    float* out = (float*)d_out;

    init_kernel<<<(BATCH * MPTS + 255) / 256, 256>>>(ptgt);
    for (int s = 0; s < NSTEPS; s++)
        step_kernel<<<TOTAL_BLKS, TPB>>>(psrc, out, s);
}